// round 5
// baseline (speedup 1.0000x reference)
#include <cuda_runtime.h>

// BlurOutwards: out = (1/20) * sum_{i=0}^{19} D^i(x), D = 3x3 max with zero padding.
// Zero padding each iteration == iterated 3x3 max on the zero-extended image.
//
// Register-resident row-streaming pipeline:
//   - 1 CTA handles a full-width (512) strip of rows of one plane.
//   - lane <-> column. 19 dilation levels live in registers per thread.
//   - vertical 3-max: registers. horizontal 3-max: warp shuffles.
//   - warp-edge columns exchanged through tiny double-buffered smem with a
//     1-row skew -> exactly one __syncthreads per row step.

#define NPIX  20
#define NLEV  19          // number of dilation levels (D^1 .. D^19)
#define IMH   512
#define IMW   512
#define TPB   512         // one thread per column
#define NW    (TPB / 32)  // 16 warps
#define SEGS  3           // vertical segments per plane
#define DELAY (2 * NLEV)  // pipeline depth in rows (38)
#define PRIME 20          // extra warmup rows before first output row

__global__ __launch_bounds__(TPB, 1)
void blur_outwards_kernel(const float* __restrict__ in,
                          float* __restrict__ out)
{
    const int plane = blockIdx.x;
    const int seg   = blockIdx.y;

    const int r0 = (IMH * seg) / SEGS;        // first output row (inclusive)
    const int r1 = (IMH * (seg + 1)) / SEGS;  // last output row (exclusive)

    const float* ip = in  + (size_t)plane * IMH * IMW;
    float*       op = out + (size_t)plane * IMH * IMW;

    const int col  = threadIdx.x;     // 0..511, always a valid column
    const int lane = col & 31;
    const int warp = col >> 5;

    // Double-buffered warp-edge exchange: [parity][level][warp]
    __shared__ float edgeL[2][NLEV][NW];   // lane 0 value of each warp
    __shared__ float edgeR[2][NLEV][NW];   // lane 31 value of each warp

    for (int k = threadIdx.x; k < 2 * NLEV * NW; k += TPB) {
        (&edgeL[0][0][0])[k] = 0.0f;
        (&edgeR[0][0][0])[k] = 0.0f;
    }
    __syncthreads();

    // Per-level pipeline state (all zero == rows before the stream are 0,
    // which matches zero-extension).
    float pend[NLEV];  // raw y_{i-1} row awaiting horizontal pass
    float h1[NLEV];    // h of previous row
    float mx[NLEV];    // max(h of prev row, h of row before that)
    float d1[NLEV];    // sum-pipeline delay regs (2-deep)
    float d2[NLEV];
#pragma unroll
    for (int i = 0; i < NLEV; ++i) {
        pend[i] = 0.0f; h1[i] = 0.0f; mx[i] = 0.0f; d1[i] = 0.0f; d2[i] = 0.0f;
    }

    const int t0   = r0 - PRIME;            // first input row fed (may be <0)
    const int tend = r1 - 1 + DELAY;        // last input row fed (may be >=IMH)

    for (int t = t0; t <= tend; ++t) {
        const int par = (t - t0) & 1;
        const int nxt = par ^ 1;

        // Ingest input row t (zero-extended outside the image).
        float v = 0.0f;
        if ((unsigned)t < (unsigned)IMH) v = ip[(size_t)t * IMW + col];

        float incoming = v;   // y_{i-1} row handed to the next level (y_0 = x)
        float sprev    = v;   // s_{i-1} row handed down (s_0 = x)

#pragma unroll
        for (int i = 0; i < NLEV; ++i) {
            // Horizontal 3-max on the buffered row (one row stale so that
            // warp-edge values are available from last step's smem writes).
            float p = pend[i];
            float l = __shfl_up_sync(0xffffffffu, p, 1);
            float r = __shfl_down_sync(0xffffffffu, p, 1);
            if (lane == 0)  l = (warp > 0)      ? edgeR[par][i][warp - 1] : 0.0f;
            if (lane == 31) r = (warp < NW - 1) ? edgeL[par][i][warp + 1] : 0.0f;
            float h0 = fmaxf(fmaxf(l, r), p);

            // Vertical 3-max (centered one row back): y_i row = pend_row - 1.
            float y = fmaxf(mx[i], h0);
            mx[i] = fmaxf(h1[i], h0);
            h1[i] = h0;

            // Sum pipeline: s_i[r] = s_{i-1}[r] + y_i[r] (2-step delay match).
            float s = d2[i] + y;
            d2[i] = d1[i];
            d1[i] = sprev;

            // Hand-offs for next step / next level.
            pend[i] = incoming;
            if (lane == 0)  edgeL[nxt][i][warp] = incoming;
            if (lane == 31) edgeR[nxt][i][warp] = incoming;
            incoming = y;
            sprev    = s;
        }

        // sprev now holds s_19[t - DELAY] = sum_{i=0}^{19} y_i at that row.
        const int orow = t - DELAY;
        if (orow >= r0 && orow < r1)
            op[(size_t)orow * IMW + col] = sprev * (1.0f / (float)NPIX);

        __syncthreads();  // separates this step's edge writes from next reads
    }
}

extern "C" void kernel_launch(void* const* d_in, const int* in_sizes, int n_in,
                              void* d_out, int out_size)
{
    const float* in = (const float*)d_in[0];
    float* out      = (float*)d_out;

    const int planes = in_sizes[0] / (IMH * IMW);   // 32*3 = 96

    dim3 grid(planes, SEGS);
    blur_outwards_kernel<<<grid, TPB>>>(in, out);
}

// round 6
// speedup vs baseline: 1.5194x; 1.5194x over previous
#include <cuda_runtime.h>

// BlurOutwards: out = (1/20) * sum_{i=0}^{19} D^i(x), D = 3x3 max, zero padding.
// Iterated zero-padded dilation == iterated 3x3 max on the zero-extended image,
// and it composes across kernel passes: D^{a+b}(x) = D^b(D^a(x)) with the
// intermediate stored zero-extended.
//
// Three chained register-pipeline passes (7 + 7 + 5 levels) so each pass keeps
// its whole level state in <=64 registers (no spills, 2 CTAs/SM).

#define IMH   512
#define IMW   512
#define TPB   512
#define NW    (TPB / 32)
#define SEGS  3
#define MAX_PLANES 96

// Static scratch for intermediate dilation planes (y7, y14).
__device__ float g_scrA[MAX_PLANES * IMH * IMW];
__device__ float g_scrB[MAX_PLANES * IMH * IMW];

// One pass of the streaming pipeline:
//   - reads input plane `in` (zero-extended outside the image)
//   - computes y_i = D^i(in) for i=1..NLEV via a register software pipeline
//   - emits   s = (FIRST ? in : 0) + sum_{i=1..NLEV} y_i
//   - sum_out[row] = (sum_in[row] if !FIRST else 0) + s   (scaled if FINAL)
//   - if WRITE_Y: y_out[row] = y_NLEV[row]
template<int NLEV, bool FIRST, bool WRITE_Y, bool FINAL>
__global__ __launch_bounds__(TPB, 2)
void blur_pass_kernel(const float* __restrict__ in,
                      const float* sum_in,
                      float* sum_out,
                      float* __restrict__ y_out)
{
    const int plane = blockIdx.x;
    const int seg   = blockIdx.y;

    const int r0 = (IMH * seg) / SEGS;
    const int r1 = (IMH * (seg + 1)) / SEGS;

    const size_t pbase = (size_t)plane * IMH * IMW;
    const float* ip = in + pbase;

    const int col  = threadIdx.x;
    const int lane = col & 31;
    const int warp = col >> 5;

    // Double-buffered warp-edge exchange: [parity][level][warp]
    __shared__ float edgeL[2][NLEV][NW];
    __shared__ float edgeR[2][NLEV][NW];
    for (int k = threadIdx.x; k < 2 * NLEV * NW; k += TPB) {
        (&edgeL[0][0][0])[k] = 0.0f;
        (&edgeR[0][0][0])[k] = 0.0f;
    }
    __syncthreads();

    // Per-level pipeline state (zero == zero-extension above the strip).
    float pend[NLEV], h1[NLEV], mx[NLEV], d1[NLEV], d2[NLEV];
#pragma unroll
    for (int i = 0; i < NLEV; ++i) {
        pend[i] = 0.0f; h1[i] = 0.0f; mx[i] = 0.0f; d1[i] = 0.0f; d2[i] = 0.0f;
    }

    const int DELAY = 2 * NLEV;
    const int t0    = r0 - NLEV;          // exact warmup: y_i[r>=r0] needs rows >= r0-NLEV
    const int tend  = r1 - 1 + DELAY;

    for (int t = t0; t <= tend; ++t) {
        const int par = (t - t0) & 1;
        const int nxt = par ^ 1;

        float v = 0.0f;
        if ((unsigned)t < (unsigned)IMH) v = ip[(size_t)t * IMW + col];

        float incoming = v;                      // y_{i-1} handed to next level
        float sprev    = FIRST ? v : 0.0f;       // running sum pipeline input

#pragma unroll
        for (int i = 0; i < NLEV; ++i) {
            // Horizontal 3-max on the one-row-stale buffered row.
            float p = pend[i];
            float l = __shfl_up_sync(0xffffffffu, p, 1);
            float r = __shfl_down_sync(0xffffffffu, p, 1);
            if (lane == 0)  l = (warp > 0)      ? edgeR[par][i][warp - 1] : 0.0f;
            if (lane == 31) r = (warp < NW - 1) ? edgeL[par][i][warp + 1] : 0.0f;
            float h0 = fmaxf(fmaxf(l, r), p);

            // Vertical 3-max (centered one row back): y_i row = t - 2i.
            float y = fmaxf(mx[i], h0);
            mx[i] = fmaxf(h1[i], h0);
            h1[i] = h0;

            // Sum pipeline with 2-row delay alignment.
            float s = d2[i] + y;
            d2[i] = d1[i];
            d1[i] = sprev;

            pend[i] = incoming;
            if (lane == 0)  edgeL[nxt][i][warp] = incoming;
            if (lane == 31) edgeR[nxt][i][warp] = incoming;
            incoming = y;
            sprev    = s;
        }

        const int orow = t - DELAY;
        if (orow >= r0 && orow < r1) {
            const size_t idx = pbase + (size_t)orow * IMW + col;
            float s = sprev;
            if (!FIRST) s += sum_in[idx];
            sum_out[idx] = FINAL ? s * 0.05f : s;
            if (WRITE_Y) y_out[idx] = incoming;   // incoming == y_NLEV[orow]
        }

        __syncthreads();
    }
}

extern "C" void kernel_launch(void* const* d_in, const int* in_sizes, int n_in,
                              void* d_out, int out_size)
{
    const float* in = (const float*)d_in[0];
    float* out      = (float*)d_out;

    const int planes = in_sizes[0] / (IMH * IMW);   // 96

    float *scrA = nullptr, *scrB = nullptr;
    cudaGetSymbolAddress((void**)&scrA, g_scrA);
    cudaGetSymbolAddress((void**)&scrB, g_scrB);

    dim3 grid(planes, SEGS);

    // Pass 1: levels 1..7 (+ the identity term), writes s(0..7) and y7.
    blur_pass_kernel<7, true,  true,  false><<<grid, TPB>>>(in,   nullptr, out, scrA);
    // Pass 2: levels 8..14, accumulates into out, writes y14.
    blur_pass_kernel<7, false, true,  false><<<grid, TPB>>>(scrA, out,     out, scrB);
    // Pass 3: levels 15..19, accumulates and scales by 1/20.
    blur_pass_kernel<5, false, false, true ><<<grid, TPB>>>(scrB, out,     out, nullptr);
}

// round 7
// speedup vs baseline: 1.9846x; 1.3062x over previous
#include <cuda_runtime.h>

// BlurOutwards: out = (1/20) * sum_{i=0}^{19} D^i(x), D = 3x3 max, zero padding.
// Iterated zero-padded dilation == iterated 3x3 max on the zero-extended image;
// composes across passes: D^{a+b}(x) = D^b(D^a(x)).
//
// Three chained register-pipeline passes (7 + 7 + 5 levels), <=64 regs each,
// 2 CTAs/SM. Branchless warp-edge exchange:
//   - zero guard slots make neighbor LDS unconditional (broadcast),
//   - shfl at warp boundary returns self, fixed by one predicated FMNMX,
//   - edge stores are single predicated STS.

#define IMH   512
#define IMW   512
#define TPB   512
#define NW    (TPB / 32)
#define SEGS  3
#define MAX_PLANES 96

// Static scratch for intermediate dilation planes (y7, y14).
__device__ float g_scrA[MAX_PLANES * IMH * IMW];
__device__ float g_scrB[MAX_PLANES * IMH * IMW];

// One pass: reads zero-extended plane `in`, computes y_i = D^i(in), i=1..NLEV,
// emits s = (FIRST ? in : 0) + sum y_i, accumulates into sum, optionally
// writes y_NLEV, optionally scales by 1/20.
template<int NLEV, bool FIRST, bool WRITE_Y, bool FINAL>
__global__ __launch_bounds__(TPB, 2)
void blur_pass_kernel(const float* __restrict__ in,
                      const float* sum_in,
                      float* sum_out,
                      float* __restrict__ y_out)
{
    const int plane = blockIdx.x;
    const int seg   = blockIdx.y;

    const int r0 = (IMH * seg) / SEGS;
    const int r1 = (IMH * (seg + 1)) / SEGS;

    const size_t pbase = (size_t)plane * IMH * IMW;
    const float* ip = in + pbase;

    const int col  = threadIdx.x;
    const int lane = col & 31;
    const int warp = col >> 5;

    // Double-buffered warp-edge exchange with zero guard slots:
    //   eR[par][i][w+1] = lane31 value of warp w;  eR[..][0]    == 0 forever
    //   eL[par][i][w+1] = lane0  value of warp w;  eL[..][NW+1] == 0 forever
    __shared__ float eR[2][NLEV][NW + 2];
    __shared__ float eL[2][NLEV][NW + 2];
    for (int k = threadIdx.x; k < 2 * NLEV * (NW + 2); k += TPB) {
        (&eR[0][0][0])[k] = 0.0f;
        (&eL[0][0][0])[k] = 0.0f;
    }
    __syncthreads();

    // Per-level pipeline state (zero == zero-extension above the strip).
    float pend[NLEV], h1[NLEV], mx[NLEV], d1[NLEV], d2[NLEV];
#pragma unroll
    for (int i = 0; i < NLEV; ++i) {
        pend[i] = 0.0f; h1[i] = 0.0f; mx[i] = 0.0f; d1[i] = 0.0f; d2[i] = 0.0f;
    }

    const int DELAY = 2 * NLEV;
    const int t0    = r0 - NLEV;           // exact warmup
    const int tend  = r1 - 1 + DELAY;

    const bool isL = (lane == 0);
    const bool isR = (lane == 31);

    for (int t = t0; t <= tend; ++t) {
        const int par = (t - t0) & 1;
        const int nxt = par ^ 1;

        float v = 0.0f;
        if ((unsigned)t < (unsigned)IMH) v = __ldg(&ip[(size_t)t * IMW + col]);

        float incoming = v;                   // y_{i-1} handed to next level
        float sprev    = FIRST ? v : 0.0f;    // running sum pipeline input

#pragma unroll
        for (int i = 0; i < NLEV; ++i) {
            // Horizontal 3-max on the one-row-stale buffered row.
            // shfl at warp edges returns self; fix with predicated FMNMX.
            float p = pend[i];
            float l = __shfl_up_sync(0xffffffffu, p, 1);
            float r = __shfl_down_sync(0xffffffffu, p, 1);
            float h0 = fmaxf(fmaxf(l, r), p);
            float le = eR[par][i][warp];       // left neighbor's right edge (or 0)
            float re = eL[par][i][warp + 2];   // right neighbor's left edge (or 0)
            if (isL) h0 = fmaxf(h0, le);
            if (isR) h0 = fmaxf(h0, re);

            // Vertical 3-max (centered one row back): y_i row = t - 2i.
            float y = fmaxf(mx[i], h0);
            mx[i] = fmaxf(h1[i], h0);
            h1[i] = h0;

            // Sum pipeline with 2-row delay alignment.
            float s = d2[i] + y;
            d2[i] = d1[i];
            d1[i] = sprev;

            pend[i] = incoming;
            if (isL) eL[nxt][i][warp + 1] = incoming;
            if (isR) eR[nxt][i][warp + 1] = incoming;
            incoming = y;
            sprev    = s;
        }

        const int orow = t - DELAY;
        if (orow >= r0 && orow < r1) {
            const size_t idx = pbase + (size_t)orow * IMW + col;
            float s = sprev;
            if (!FIRST) s += sum_in[idx];
            sum_out[idx] = FINAL ? s * 0.05f : s;
            if (WRITE_Y) y_out[idx] = incoming;   // incoming == y_NLEV[orow]
        }

        __syncthreads();  // separates this step's edge writes from next reads
    }
}

extern "C" void kernel_launch(void* const* d_in, const int* in_sizes, int n_in,
                              void* d_out, int out_size)
{
    const float* in = (const float*)d_in[0];
    float* out      = (float*)d_out;

    const int planes = in_sizes[0] / (IMH * IMW);   // 96

    float *scrA = nullptr, *scrB = nullptr;
    cudaGetSymbolAddress((void**)&scrA, g_scrA);
    cudaGetSymbolAddress((void**)&scrB, g_scrB);

    dim3 grid(planes, SEGS);

    // Pass 1: levels 1..7 (+ identity term), writes s(0..7) and y7.
    blur_pass_kernel<7, true,  true,  false><<<grid, TPB>>>(in,   nullptr, out, scrA);
    // Pass 2: levels 8..14, accumulates into out, writes y14.
    blur_pass_kernel<7, false, true,  false><<<grid, TPB>>>(scrA, out,     out, scrB);
    // Pass 3: levels 15..19, accumulates and scales by 1/20.
    blur_pass_kernel<5, false, false, true ><<<grid, TPB>>>(scrB, out,     out, nullptr);
}